// round 14
// baseline (speedup 1.0000x reference)
#include <cuda_runtime.h>
#include <cstdint>

#define H 128
#define W 128
#define NS 8
#define TY 32
#define SROWS (TY + 8)    // 40
#define EC    70          // entries per parity row (max index 68 + pad, even)

typedef unsigned long long u64;

__device__ __forceinline__ void fma2(u64& acc, u64 a, u64 b) {
    asm("fma.rn.f32x2 %0, %1, %2, %0;" : "+l"(acc) : "l"(a), "l"(b));
}
__device__ __forceinline__ void mul2(u64& d, u64 a, u64 b) {
    asm("mul.rn.f32x2 %0, %1, %2;" : "=l"(d) : "l"(a), "l"(b));
}
__device__ __forceinline__ u64 pk(float lo, float hi) {
    u64 r; asm("mov.b64 %0, {%1, %2};" : "=l"(r) : "f"(lo), "f"(hi)); return r;
}
__device__ __forceinline__ void unpk(u64 v, float& lo, float& hi) {
    asm("mov.b64 {%0, %1}, %2;" : "=f"(lo), "=f"(hi) : "l"(v));
}
__device__ __forceinline__ u64 as_u64(float2 v) {
    return reinterpret_cast<u64&>(v);
}

// One s-group, one warp: 8 output rows x 4 cols/lane, sliding accumulator.
// A4 = a & 3 (a = 4 - sx). m0 = (a+1)>>1 (parity-0 start), m1 = a>>1.
// bp0/bp1 point at &s_p[p][rowbase][2*lane + (m_p & ~1)].
// Tap t -> parity (A4+t)&1, slot t>>1. Per parity, slots j=0..2 are pairs at
// entry-starts m_p+j; reconstructed from aligned LDS.64 at m̄, m̄+2 (,m̄+4).
template<int A4>
__device__ __forceinline__ void conv_s(const float* __restrict__ bp0,
                                       const float* __restrict__ bp1,
                                       const u64* __restrict__ fp,
                                       float* __restrict__ ops)
{
    constexpr int M0ODD = (((A4 + 1) >> 1) & 1);
    constexpr int M1ODD = ((A4 >> 1) & 1);

    u64 acc[8][2];
    #pragma unroll
    for (int k = 0; k < 12; ++k) {
        const float2* r0 = (const float2*)(bp0 + k * EC);
        const float2* r1 = (const float2*)(bp1 + k * EC);

        u64 tap0[3], tap1[3];
        {
            float2 A = r0[0], B = r0[1];
            if (M0ODD) {
                float2 C = r0[2];
                tap0[0] = pk(A.y, B.x); tap0[1] = as_u64(B); tap0[2] = pk(B.y, C.x);
            } else {
                tap0[0] = as_u64(A); tap0[1] = pk(A.y, B.x); tap0[2] = as_u64(B);
            }
        }
        {
            float2 A = r1[0], B = r1[1];
            if (M1ODD) {
                float2 C = r1[2];
                tap1[0] = pk(A.y, B.x); tap1[1] = as_u64(B); tap1[2] = pk(B.y, C.x);
            } else {
                tap1[0] = as_u64(A); tap1[1] = pk(A.y, B.x); tap1[2] = as_u64(B);
            }
        }
        u64 q[6];
        #pragma unroll
        for (int t = 0; t < 6; ++t)
            q[t] = (((A4 + t) & 1) == 0) ? tap0[t >> 1] : tap1[t >> 1];

        #pragma unroll
        for (int y = 0; y < 8; ++y) {
            const int i = k - y;               // compile-time after unroll
            if (i == 0) {
                mul2(acc[y][0], fp[0], q[0]);
                mul2(acc[y][1], fp[0], q[1]);
                #pragma unroll
                for (int j = 1; j < 5; ++j) {
                    fma2(acc[y][0], fp[j], q[j]);
                    fma2(acc[y][1], fp[j], q[j + 1]);
                }
            } else if (i >= 1 && i < 5) {
                #pragma unroll
                for (int j = 0; j < 5; ++j) {
                    fma2(acc[y][0], fp[i * 5 + j], q[j]);
                    fma2(acc[y][1], fp[i * 5 + j], q[j + 1]);
                }
            }
        }
        const int yd = k - 4;                  // row done: store & retire
        if (yd >= 0 && yd < 8) {
            float o0, o2, o1, o3;
            unpk(acc[yd][0], o0, o2);
            unpk(acc[yd][1], o1, o3);
            *(float4*)(ops + yd * W) = make_float4(o0, o1, o2, o3);
        }
    }
}

__global__ void __launch_bounds__(128, 6)
shifted_conv_kernel(const float* __restrict__ tens,
                    const float* __restrict__ filters,
                    const int* __restrict__ shifts,
                    float* __restrict__ out)
{
    // Single parity-deinterleaved copy: s_p[p][r][i] = x_pad[r][2i+p]
    __shared__ __align__(16) float s_p[2][SROWS][EC];     // 22.4 KB
    __shared__ __align__(16) float2 s_fp[NS][25];         // splatted (f,f)
    __shared__ int s_sh[NS * 2];

    const int n    = blockIdx.x;
    const int y0   = blockIdx.y * TY;   // 0,32,64,96
    const int tid  = threadIdx.x;
    const int lane = tid & 31;
    const int wrp  = tid >> 5;

    for (int i = tid; i < NS * 25; i += 128) {
        float f = filters[i];
        s_fp[i / 25][i % 25] = make_float2(f, f);
    }
    if (tid < NS * 2) s_sh[tid] = shifts[tid];

    const float* inp = tens + (size_t)n * (H * W);
    for (int idx = tid; idx < SROWS * (2 * EC); idx += 128) {
        int r  = idx / (2 * EC);
        int c  = idx - r * (2 * EC);    // padded col 0..139 (>=136 -> OOB -> 0)
        int gy = y0 - 4 + r;
        int gx = c - 4;
        float v = 0.0f;
        if (gy >= 0 && gy < H && gx >= 0 && gx < W)
            v = inp[gy * W + gx];
        s_p[c & 1][r][c >> 1] = v;
    }
    __syncthreads();

    const int ybase = wrp * 8;          // 8 output rows per warp (rotation)
    const int xo    = 4 * lane;
    float* outw = out + (size_t)n * (NS * H * W)
                      + (size_t)(y0 + ybase) * W + xo;

    #pragma unroll 1
    for (int s = 0; s < NS; ++s) {
        const int sy = s_sh[2 * s + 0];
        const int sx = s_sh[2 * s + 1];

        u64 fp[25];
        #pragma unroll
        for (int t = 0; t < 25; ++t) fp[t] = as_u64(s_fp[s][t]);

        const int rowbase = ybase + 4 - sy;   // [0, 28]
        const int a       = 4 - sx;           // [0, 4]
        const int m0      = (a + 1) >> 1;     // parity-0 pair start
        const int m1      = a >> 1;           // parity-1 pair start

        const float* bp0 = &s_p[0][rowbase][2 * lane + (m0 & ~1)];
        const float* bp1 = &s_p[1][rowbase][2 * lane + (m1 & ~1)];
        float* ops = outw + (size_t)s * (H * W);

        switch (a & 3) {
            case 0: conv_s<0>(bp0, bp1, fp, ops); break;
            case 1: conv_s<1>(bp0, bp1, fp, ops); break;
            case 2: conv_s<2>(bp0, bp1, fp, ops); break;
            default: conv_s<3>(bp0, bp1, fp, ops); break;
        }
    }
}

extern "C" void kernel_launch(void* const* d_in, const int* in_sizes, int n_in,
                              void* d_out, int out_size)
{
    const float* tens    = (const float*)d_in[0];
    const float* filters = (const float*)d_in[1];
    const int*   shifts  = (const int*)d_in[2];
    float*       out     = (float*)d_out;

    dim3 grid(256, H / TY);   // 1024 blocks
    shifted_conv_kernel<<<grid, 128>>>(tens, filters, shifts, out);
}

// round 15
// speedup vs baseline: 1.2292x; 1.2292x over previous
#include <cuda_runtime.h>
#include <cstdint>

#define H 128
#define W 128
#define NS 8
#define TY 32
#define SROWS (TY + 8)    // 40
#define SCOLS 136         // x_pad[c] = x[c-4], c in [0,136)
#define EC    (SCOLS / 2) // 68 entries per parity row

typedef unsigned long long u64;

__device__ __forceinline__ void fma2(u64& acc, u64 a, u64 b) {
    asm("fma.rn.f32x2 %0, %1, %2, %0;" : "+l"(acc) : "l"(a), "l"(b));
}
__device__ __forceinline__ void mul2(u64& d, u64 a, u64 b) {
    asm("mul.rn.f32x2 %0, %1, %2;" : "=l"(d) : "l"(a), "l"(b));
}
__device__ __forceinline__ void unpk(u64 v, float& lo, float& hi) {
    asm("mov.b64 {%0, %1}, %2;" : "=f"(lo), "=f"(hi) : "l"(v));
}

__global__ void __launch_bounds__(128)
shifted_conv_kernel(const float* __restrict__ tens,
                    const float* __restrict__ filters,
                    const int* __restrict__ shifts,
                    float* __restrict__ out)
{
    // Parity-deinterleaved tile, two copies per parity shifted by one entry:
    //   s_p[p][0][r][i] = x_pad[r][2i+p]
    //   s_p[p][1][r][i] = x_pad[r][2i+p+2]
    __shared__ __align__(16) float s_p[2][2][SROWS][EC];   // 43.5 KB
    __shared__ __align__(16) float2 s_fp[NS][25];          // splatted (f,f)
    __shared__ int s_sh[NS * 2];

    const int n    = blockIdx.x;
    const int y0   = blockIdx.y * TY;   // 0,32,64,96
    const int tid  = threadIdx.x;
    const int lane = tid & 31;
    const int wrp  = tid >> 5;

    for (int i = tid; i < NS * 25; i += 128) {
        float f = filters[i];
        s_fp[i / 25][i % 25] = make_float2(f, f);
    }
    if (tid < NS * 2) s_sh[tid] = shifts[tid];

    const float* inp = tens + (size_t)n * (H * W);
    for (int idx = tid; idx < SROWS * SCOLS; idx += 128) {
        int r  = idx / SCOLS;
        int c  = idx - r * SCOLS;
        int gy = y0 - 4 + r;
        int gx = c - 4;
        float v = 0.0f;
        if (gy >= 0 && gy < H && gx >= 0 && gx < W)
            v = inp[gy * W + gx];
        int p = c & 1, i = c >> 1;
        s_p[p][0][r][i] = v;
        if (i > 0) s_p[p][1][r][i - 1] = v;
    }
    for (int r = tid; r < SROWS; r += 128) {   // copy1 tails: x_pad[136/137]=0
        s_p[0][1][r][EC - 1] = 0.0f;
        s_p[1][1][r][EC - 1] = 0.0f;
    }
    __syncthreads();

    // Warp-level s-split: warp handles 4 s-groups over 16 output rows.
    //   rows:  ybase = (wrp & 1) * 16
    //   s:     sbase = (wrp >> 1) * 4
    const int ybase = (wrp & 1) * 16;
    const int sbase = (wrp >> 1) * 4;
    const int xo    = 4 * lane;
    float* outw = out + (size_t)n * (NS * H * W)
                      + (size_t)(y0 + ybase) * W + xo;

    #pragma unroll 1
    for (int s = sbase; s < sbase + 4; ++s) {
        const int sy = s_sh[2 * s + 0];
        const int sx = s_sh[2 * s + 1];

        // Filter splat pairs: 25 aligned LDS.64, reused for 16 rows now.
        u64 fp[25];
        #pragma unroll
        for (int t = 0; t < 25; ++t) {
            float2 v = s_fp[s][t];
            fp[t] = reinterpret_cast<u64&>(v);
        }

        const int rowbase = ybase + 4 - sy;   // [ybase, ybase+4]
        const int a       = 4 - sx;           // [0, 4]
        // Pair t = (x_pad[c0+t], x_pad[c0+t+2]), c0 = xo + a. Same-parity
        // adjacent entries; copy index gives 8B alignment. (Verified R11/12.)
        const float* bp[6];
        #pragma unroll
        for (int t = 0; t < 6; ++t) {
            int p = (a + t) & 1;
            int h = (a + t - p) >> 1;
            bp[t] = &s_p[p][h & 1][rowbase][2 * lane + (h & ~1)];
        }

        float* ops = outw + (size_t)s * (H * W);

        // Sliding rotation over 20 input rows for 16 output rows; output row
        // y is live for k in [y, y+4]; store right after last tap -> <=5
        // accumulator rows live at any time.
        u64 acc[16][2];
        #pragma unroll
        for (int k = 0; k < 20; ++k) {
            u64 q[6];
            #pragma unroll
            for (int t = 0; t < 6; ++t) {
                float2 v = *(const float2*)(bp[t] + k * EC);  // aligned LDS.64
                q[t] = reinterpret_cast<u64&>(v);
            }
            #pragma unroll
            for (int y = 0; y < 16; ++y) {
                const int i = k - y;           // compile-time after unroll
                if (i == 0) {
                    mul2(acc[y][0], fp[0], q[0]);
                    mul2(acc[y][1], fp[0], q[1]);
                    #pragma unroll
                    for (int j = 1; j < 5; ++j) {
                        fma2(acc[y][0], fp[j], q[j]);
                        fma2(acc[y][1], fp[j], q[j + 1]);
                    }
                } else if (i >= 1 && i < 5) {
                    #pragma unroll
                    for (int j = 0; j < 5; ++j) {
                        fma2(acc[y][0], fp[i * 5 + j], q[j]);
                        fma2(acc[y][1], fp[i * 5 + j], q[j + 1]);
                    }
                }
            }
            const int yd = k - 4;              // row finished: store & retire
            if (yd >= 0 && yd < 16) {
                float o0, o2, o1, o3;
                unpk(acc[yd][0], o0, o2);
                unpk(acc[yd][1], o1, o3);
                *(float4*)(ops + yd * W) = make_float4(o0, o1, o2, o3);
            }
        }
    }
}

extern "C" void kernel_launch(void* const* d_in, const int* in_sizes, int n_in,
                              void* d_out, int out_size)
{
    const float* tens    = (const float*)d_in[0];
    const float* filters = (const float*)d_in[1];
    const int*   shifts  = (const int*)d_in[2];
    float*       out     = (float*)d_out;

    dim3 grid(256, H / TY);   // 1024 blocks
    shifted_conv_kernel<<<grid, 128>>>(tens, filters, shifts, out);
}